// round 1
// baseline (speedup 1.0000x reference)
#include <cuda_runtime.h>
#include <cstdint>

// Problem constants (fixed shapes per reference):
//   N=128, T=256, E=6, D=10
//   merged   : (128,256,14)  fp32  -- UNUSED
//   y_pred_i : (128,256,6)   fp32
//   y_pred_ij: (128,128,256,6) fp32  (dominant: ~100.7 MB)
//   input1   : (128,256,15)  fp32  (err_true = cols 7..12)
//   samples  : (128,10)      fp32
//   labels   : (128,)        int64 -- UNUSED
// Output: scalar fp32 L_sim.

#define NPAIR 128
#define TE 1536              // T*E = 256*6
#define TE4 384              // TE/4

// Scratch for second[i][j] (16384 floats). Device global (no allocs allowed).
__device__ float g_second[NPAIR * NPAIR];

// ---------------------------------------------------------------------------
// Kernel 1: second[i,j] = sum_{t,e} (yij[i,j,t,e] - yi[j,t,e])^2
//                         / err[j,t,e]^2  / (T*E*10)
// grid = (j: 128, i_grp: 8), block = 256 threads (8 warps).
// Each block stages w[j] (scale/err^2) and y_pred_i[j] in shared memory,
// then each warp processes 2 values of i (i_grp*16 + warp*2 + {0,1}).
// y_pred_ij reads are contiguous float4, fully coalesced, 24 independent
// loads in flight per warp.
// ---------------------------------------------------------------------------
__global__ void __launch_bounds__(256)
second_kernel(const float* __restrict__ yij,
              const float* __restrict__ yi,
              const float* __restrict__ in1,
              float* __restrict__ out)
{
    __shared__ float4 w_s[TE4];
    __shared__ float4 y_s[TE4];

    const int j   = blockIdx.x;
    const int grp = blockIdx.y;
    const int tid = threadIdx.x;

    // Build weight tile w[j,t,e] = (1/15360) / err^2, and stage y_pred_i[j].
    const float scale = 1.0f / 15360.0f;   // 1/(T*E*10)
    float*  w_f = reinterpret_cast<float*>(w_s);
    float*  y_f = reinterpret_cast<float*>(y_s);
    #pragma unroll
    for (int idx = tid; idx < TE; idx += 256) {
        int t = idx / 6;
        int c = idx - t * 6;
        float e = in1[(j * 256 + t) * 15 + 7 + c];
        w_f[idx] = scale / (e * e);
        y_f[idx] = yi[j * TE + idx];
    }

    // Zero the output once (d_out is poisoned by the harness). Kernel 2 only
    // runs after this kernel completes, so ordering is safe.
    if (j == 0 && grp == 0 && tid == 0) out[0] = 0.0f;

    __syncthreads();

    const int warp = tid >> 5;
    const int lane = tid & 31;
    const int i0   = grp * 16 + warp * 2;     // this warp's two i rows

    const float4* p0 = reinterpret_cast<const float4*>(
        yij + (size_t)(i0 * NPAIR + j) * TE);
    const float4* p1 = reinterpret_cast<const float4*>(
        yij + (size_t)((i0 + 1) * NPAIR + j) * TE);

    float a0 = 0.0f, a1 = 0.0f;
    #pragma unroll
    for (int k = 0; k < 12; ++k) {
        const int x = lane + 32 * k;
        const float4 wv = w_s[x];
        const float4 yv = y_s[x];
        const float4 g0 = p0[x];
        const float4 g1 = p1[x];
        float d;
        d = g0.x - yv.x; a0 = fmaf(d * d, wv.x, a0);
        d = g0.y - yv.y; a0 = fmaf(d * d, wv.y, a0);
        d = g0.z - yv.z; a0 = fmaf(d * d, wv.z, a0);
        d = g0.w - yv.w; a0 = fmaf(d * d, wv.w, a0);
        d = g1.x - yv.x; a1 = fmaf(d * d, wv.x, a1);
        d = g1.y - yv.y; a1 = fmaf(d * d, wv.y, a1);
        d = g1.z - yv.z; a1 = fmaf(d * d, wv.z, a1);
        d = g1.w - yv.w; a1 = fmaf(d * d, wv.w, a1);
    }

    // Warp tree reduction.
    #pragma unroll
    for (int o = 16; o; o >>= 1) {
        a0 += __shfl_xor_sync(0xFFFFFFFFu, a0, o);
        a1 += __shfl_xor_sync(0xFFFFFFFFu, a1, o);
    }
    if (lane == 0) {
        g_second[i0 * NPAIR + j]       = a0;
        g_second[(i0 + 1) * NPAIR + j] = a1;
    }
}

// ---------------------------------------------------------------------------
// Kernel 2: L_sim = mean_{i,j} | S_ij - 0.5*(second[i,j] + second[j,i]) |
//           S_ij = mean_d (samples[i,d]-samples[j,d])^2
// grid = 128 (i), block = 128 (j). One atomicAdd per block.
// ---------------------------------------------------------------------------
__global__ void __launch_bounds__(128)
final_kernel(const float* __restrict__ samples,
             float* __restrict__ out)
{
    __shared__ float si[10];
    __shared__ float part[4];

    const int i = blockIdx.x;
    const int j = threadIdx.x;

    if (j < 10) si[j] = samples[i * 10 + j];
    __syncthreads();

    float S = 0.0f;
    #pragma unroll
    for (int d = 0; d < 10; ++d) {
        float df = samples[j * 10 + d] - si[d];
        S = fmaf(df, df, S);
    }
    S *= 0.1f;   // mean over D=10

    float avg = 0.5f * (g_second[i * NPAIR + j] + g_second[j * NPAIR + i]);
    float v = fabsf(S - avg);

    #pragma unroll
    for (int o = 16; o; o >>= 1)
        v += __shfl_xor_sync(0xFFFFFFFFu, v, o);

    if ((j & 31) == 0) part[j >> 5] = v;
    __syncthreads();

    if (j == 0) {
        float blk = part[0] + part[1] + part[2] + part[3];
        atomicAdd(out, blk * (1.0f / 16384.0f));
    }
}

// ---------------------------------------------------------------------------
extern "C" void kernel_launch(void* const* d_in, const int* in_sizes, int n_in,
                              void* d_out, int out_size)
{
    (void)in_sizes; (void)n_in; (void)out_size;
    // d_in order per metadata: merged, y_pred_i, y_pred_ij, input1, samples, labels
    const float* yi      = (const float*)d_in[1];
    const float* yij     = (const float*)d_in[2];
    const float* in1     = (const float*)d_in[3];
    const float* samples = (const float*)d_in[4];
    float* out = (float*)d_out;

    dim3 grid1(NPAIR, 8);
    second_kernel<<<grid1, 256>>>(yij, yi, in1, out);
    final_kernel<<<NPAIR, 128>>>(samples, out);
}